// round 16
// baseline (speedup 1.0000x reference)
#include <cuda_runtime.h>
#include <math.h>
#include <stdint.h>

#define S_LEN 2048
#define HID   4096
#define NH    32
#define NKV   8
#define HD    128

// -------- scratch (device globals; no allocation allowed) --------
__device__ float g_Q[S_LEN * NH * HD];     // 32 MB
__device__ float g_K[S_LEN * NKV * HD];    // 8 MB
__device__ float g_V[S_LEN * NKV * HD];    // 8 MB
__device__ float g_attn[S_LEN * NH * HD];  // 32 MB

// ---------------- tf32 helpers ----------------
__device__ __forceinline__ uint32_t frag_tf32(float x) {
    uint32_t u;
    asm("cvt.rna.tf32.f32 %0, %1;" : "=r"(u) : "f"(x));
    return u;
}

__device__ __forceinline__ void mma_tf32(float& d0, float& d1, float& d2, float& d3,
                                         uint32_t a0, uint32_t a1, uint32_t a2, uint32_t a3,
                                         uint32_t b0, uint32_t b1) {
    asm volatile(
        "mma.sync.aligned.m16n8k8.row.col.f32.tf32.tf32.f32 "
        "{%0,%1,%2,%3}, {%4,%5,%6,%7}, {%8,%9}, {%0,%1,%2,%3};"
        : "+f"(d0), "+f"(d1), "+f"(d2), "+f"(d3)
        : "r"(a0), "r"(a1), "r"(a2), "r"(a3), "r"(b0), "r"(b1));
}

__device__ __forceinline__ void cp_async16(uint32_t smem_addr, const void* gptr) {
    asm volatile("cp.async.cg.shared.global [%0], [%1], 16;\n"
                 :: "r"(smem_addr), "l"(gptr));
}
__device__ __forceinline__ void cp_commit() {
    asm volatile("cp.async.commit_group;\n" ::: "memory");
}
template <int N>
__device__ __forceinline__ void cp_wait() {
    asm volatile("cp.async.wait_group %0;\n" :: "n"(N) : "memory");
}

// L2-locality swizzle (kept from R15: small but positive)
__device__ __forceinline__ void swizzle_bid(int& bm, int& bn) {
    const int gx = gridDim.x, gy = gridDim.y;
    int lin  = blockIdx.y * gx + blockIdx.x;
    int band = 16 * gy;
    int gid  = lin / band;
    int rem  = lin - gid * band;
    bn = gid * 16 + (rem & 15);
    bm = rem >> 4;
}

// ============ TF32 GEMM core (shared by generic + fused-QKV kernels) ============
#define APITCH 20
#define BPITCH 136
#define A_ELEMS (128 * APITCH)
#define B_ELEMS (16 * BPITCH)
#define STAGE_ELEMS (A_ELEMS + B_ELEMS)
#define NSTAGE 3

__device__ __forceinline__ void gemm_tile_tf32(
    const float* __restrict__ Ag0, int K,
    const float* __restrict__ Bg0, int NB,
    float* __restrict__ Ct, int NC, float* smem)
{
    const int tid  = threadIdx.x;
    const int lane = tid & 31;
    const int wid  = tid >> 5;
    const int warp_m = wid & 1;
    const int warp_n = wid >> 1;
    const int r = lane >> 2;
    const int c = lane & 3;

    const int am  = tid >> 1;
    const int ak8 = (tid & 1) * 8;
    const int bk  = tid >> 4;
    const int bn0 = (tid & 15) * 8;

    const float* Ag = Ag0 + (size_t)am * K + ak8;
    const float* Bg = Bg0 + (size_t)bk * NB + bn0;

    uint32_t smem_base;
    asm("{ .reg .u64 t; cvta.to.shared.u64 t, %1; cvt.u32.u64 %0, t; }"
        : "=r"(smem_base) : "l"(smem));

    float acc[4][4][4];
#pragma unroll
    for (int f = 0; f < 4; f++)
#pragma unroll
        for (int g = 0; g < 4; g++)
#pragma unroll
            for (int x = 0; x < 4; x++) acc[f][g][x] = 0.f;

    const int ntiles = K >> 4;

#pragma unroll
    for (int pf = 0; pf < 2; pf++) {
        uint32_t sa = smem_base + (pf * STAGE_ELEMS + am * APITCH + ak8) * 4;
        cp_async16(sa,      Ag + (size_t)pf * 16);
        cp_async16(sa + 16, Ag + (size_t)pf * 16 + 4);
        uint32_t sb = smem_base + (pf * STAGE_ELEMS + A_ELEMS + bk * BPITCH + bn0) * 4;
        cp_async16(sb,      Bg + (size_t)pf * 16 * NB);
        cp_async16(sb + 16, Bg + (size_t)pf * 16 * NB + 4);
        cp_commit();
    }

    for (int kt = 0; kt < ntiles; kt++) {
        cp_wait<1>();
        __syncthreads();

        if (kt + 2 < ntiles) {
            int st = (kt + 2) % NSTAGE;
            uint32_t sa = smem_base + (st * STAGE_ELEMS + am * APITCH + ak8) * 4;
            cp_async16(sa,      Ag + (size_t)(kt + 2) * 16);
            cp_async16(sa + 16, Ag + (size_t)(kt + 2) * 16 + 4);
            uint32_t sb = smem_base + (st * STAGE_ELEMS + A_ELEMS + bk * BPITCH + bn0) * 4;
            cp_async16(sb,      Bg + (size_t)(kt + 2) * 16 * NB);
            cp_async16(sb + 16, Bg + (size_t)(kt + 2) * 16 * NB + 4);
        }
        cp_commit();

        const float* As = smem + (kt % NSTAGE) * STAGE_ELEMS;
        const float* Bs = As + A_ELEMS;

#pragma unroll
        for (int s = 0; s < 2; s++) {
            const int k0 = s * 8;
            uint32_t af[4][4], bf[4][2];
#pragma unroll
            for (int f = 0; f < 4; f++) {
                const int mb = warp_m * 64 + f * 16;
                af[f][0] = frag_tf32(As[(mb + r    ) * APITCH + k0 + c    ]);
                af[f][1] = frag_tf32(As[(mb + r + 8) * APITCH + k0 + c    ]);
                af[f][2] = frag_tf32(As[(mb + r    ) * APITCH + k0 + c + 4]);
                af[f][3] = frag_tf32(As[(mb + r + 8) * APITCH + k0 + c + 4]);
            }
#pragma unroll
            for (int g = 0; g < 4; g++) {
                const int nb = warp_n * 32 + g * 8;
                bf[g][0] = frag_tf32(Bs[(k0 + c    ) * BPITCH + nb + r]);
                bf[g][1] = frag_tf32(Bs[(k0 + c + 4) * BPITCH + nb + r]);
            }
#pragma unroll
            for (int f = 0; f < 4; f++)
#pragma unroll
                for (int g = 0; g < 4; g++)
                    mma_tf32(acc[f][g][0], acc[f][g][1], acc[f][g][2], acc[f][g][3],
                             af[f][0], af[f][1], af[f][2], af[f][3],
                             bf[g][0], bf[g][1]);
        }
    }

#pragma unroll
    for (int f = 0; f < 4; f++) {
        const int row0 = warp_m * 64 + f * 16 + r;
#pragma unroll
        for (int g = 0; g < 4; g++) {
            const int col0 = warp_n * 32 + g * 8 + 2 * c;
            *(float2*)&Ct[(size_t)row0 * NC + col0]       = make_float2(acc[f][g][0], acc[f][g][1]);
            *(float2*)&Ct[(size_t)(row0 + 8) * NC + col0] = make_float2(acc[f][g][2], acc[f][g][3]);
        }
    }
}

__global__ __launch_bounds__(256, 2)
void sgemm_tf32(const float* __restrict__ A, const float* __restrict__ B,
                float* __restrict__ C, int M, int N, int K)
{
    extern __shared__ float smem[];
    int bm, bn;
    swizzle_bid(bm, bn);
    gemm_tile_tf32(A + (size_t)bm * 128 * K, K,
                   B + (size_t)bn * 128, N,
                   C + (size_t)bm * 128 * N + (size_t)bn * 128, N, smem);
}

__global__ __launch_bounds__(256, 2)
void sgemm_tf32_qkv(const float* __restrict__ X,
                    const float* __restrict__ Wq, const float* __restrict__ Wk,
                    const float* __restrict__ Wv,
                    float* __restrict__ Qo, float* __restrict__ Ko,
                    float* __restrict__ Vo)
{
    extern __shared__ float smem[];
    int bm, bn;
    swizzle_bid(bm, bn);

    const float* Bb;
    float* Cb;
    int Nw, bnl;
    if (bn < 32)      { Bb = Wq; Cb = Qo; Nw = NH * HD;  bnl = bn; }
    else if (bn < 40) { Bb = Wk; Cb = Ko; Nw = NKV * HD; bnl = bn - 32; }
    else              { Bb = Wv; Cb = Vo; Nw = NKV * HD; bnl = bn - 40; }

    gemm_tile_tf32(X + (size_t)bm * 128 * HID, HID,
                   Bb + (size_t)bnl * 128, Nw,
                   Cb + (size_t)bm * 128 * Nw + (size_t)bnl * 128, Nw, smem);
}

// ================= llama3-smoothed RoPE, in place, fp32, float4 =================
__global__ __launch_bounds__(256)
void rope_kernel(float* __restrict__ x, int nheads)
{
    int idx = blockIdx.x * blockDim.x + threadIdx.x;
    int total = S_LEN * nheads * 16;
    if (idx >= total) return;
    int g = idx & 15;
    int h = (idx >> 4) % nheads;
    int s = idx / (16 * nheads);

    const float LOG2_BASE = 18.93156856932417f;   // log2(500000)
    const float TWO_PI    = 6.283185307179586f;

    float* row = x + (size_t)s * nheads * HD + h * HD;
    float4 v1 = *(float4*)&row[g * 4];
    float4 v2 = *(float4*)&row[g * 4 + 64];

    float o1[4], o2[4];
#pragma unroll
    for (int t = 0; t < 4; t++) {
        int i = g * 4 + t;
        float inv_freq = exp2f(-((float)(2 * i) / 128.0f) * LOG2_BASE);
        float wavelen  = TWO_PI / inv_freq;
        float smooth   = (8192.0f / wavelen - 1.0f) * (1.0f / 3.0f);
        smooth = fminf(1.0f, fmaxf(0.0f, smooth));
        float freq = (1.0f - smooth) * (inv_freq * 0.125f) + smooth * inv_freq;

        float c, sn;
        sincosf((float)s * freq, &sn, &c);
        float x1 = (&v1.x)[t], x2 = (&v2.x)[t];
        o1[t] = x1 * c - x2 * sn;
        o2[t] = x2 * c + x1 * sn;
    }
    *(float4*)&row[g * 4]      = make_float4(o1[0], o1[1], o1[2], o1[3]);
    *(float4*)&row[g * 4 + 64] = make_float4(o2[0], o2[1], o2[2], o2[3]);
}

// ================= Flash attention (causal, GQA), fp32, BQ=128, 512 threads ====
// grid: (16 q-tiles, 32 heads), 512 threads (tx 16 x ty 32).
// Thread tile: QK 4x4, PV 4x8. Per-output fma order identical to 256-thread ver.
// smem: Qs[128][132], KVs[64][132] (K then V), Ps[128][65]  -> 134656 B
#define BQ 128
#define BKV 64
#define KSTR 132
#define PSTR 65

__global__ __launch_bounds__(512, 1)
void flash_kernel(const float* __restrict__ Q, const float* __restrict__ K,
                  const float* __restrict__ V, float* __restrict__ O)
{
    extern __shared__ float sm[];
    float* Qs  = sm;                         // [128][132]
    float* KVs = sm + BQ * KSTR;             // [64][132]
    float* Ps  = sm + BQ * KSTR + BKV * KSTR;// [128][65]

    const int qt  = gridDim.x - 1 - blockIdx.x;   // longest blocks first
    const int h   = blockIdx.y;
    const int kvh = h >> 2;
    const int tid = threadIdx.x;
    const int tx = tid & 15, ty = tid >> 4;       // tx 0..15, ty 0..31
    const int q0 = qt * BQ;
    const float scale = 0.08838834764831845f;

    // load Q tile (coalesced float4): 128 rows x 32 float4
    for (int t = tid; t < BQ * 32; t += 512) {
        int r = t >> 5, c4 = (t & 31) << 2;
        *(float4*)&Qs[r * KSTR + c4] =
            *(const float4*)&Q[(size_t)(q0 + r) * (NH * HD) + h * HD + c4];
    }

    float m_i[4], l_i[4], o_acc[4][8];
#pragma unroll
    for (int i = 0; i < 4; i++) {
        m_i[i] = -INFINITY;
        l_i[i] = 0.f;
#pragma unroll
        for (int j = 0; j < 8; j++) o_acc[i][j] = 0.f;
    }

    const int njt = 2 * qt + 2;   // kv tiles of 64 covering q0+127
    for (int j = 0; j < njt; j++) {
        const int k0 = j * BKV;
        __syncthreads();   // prev PV done reading KVs; Qs ready (iter 0)
        for (int t = tid; t < BKV * 32; t += 512) {
            int r = t >> 5, c4 = (t & 31) << 2;
            *(float4*)&KVs[r * KSTR + c4] =
                *(const float4*)&K[(size_t)(k0 + r) * (NKV * HD) + kvh * HD + c4];
        }
        __syncthreads();

        // ---- S = Q K^T (4x4 per thread) ----
        float sacc[4][4];
#pragma unroll
        for (int i = 0; i < 4; i++)
#pragma unroll
            for (int jj = 0; jj < 4; jj++) sacc[i][jj] = 0.f;

#pragma unroll 8
        for (int d = 0; d < HD; d += 4) {
            float4 qa[4], kb[4];
#pragma unroll
            for (int i = 0; i < 4; i++)
                qa[i] = *(const float4*)&Qs[(ty * 4 + i) * KSTR + d];
#pragma unroll
            for (int i = 0; i < 4; i++)
                kb[i] = *(const float4*)&KVs[(tx * 4 + i) * KSTR + d];
#pragma unroll
            for (int i = 0; i < 4; i++)
#pragma unroll
                for (int jj = 0; jj < 4; jj++) {
                    sacc[i][jj] = fmaf(qa[i].x, kb[jj].x, sacc[i][jj]);
                    sacc[i][jj] = fmaf(qa[i].y, kb[jj].y, sacc[i][jj]);
                    sacc[i][jj] = fmaf(qa[i].z, kb[jj].z, sacc[i][jj]);
                    sacc[i][jj] = fmaf(qa[i].w, kb[jj].w, sacc[i][jj]);
                }
        }

        // ---- scale + causal mask (last two tiles only) ----
        const bool diag = (j >= njt - 2);
#pragma unroll
        for (int i = 0; i < 4; i++)
#pragma unroll
            for (int jj = 0; jj < 4; jj++) {
                float v = sacc[i][jj] * scale;
                if (diag && (k0 + tx * 4 + jj) > (q0 + ty * 4 + i)) v = -INFINITY;
                sacc[i][jj] = v;
            }

        // ---- online softmax (reduce over tx within half-warp of 16) ----
#pragma unroll
        for (int i = 0; i < 4; i++) {
            float mt = fmaxf(fmaxf(sacc[i][0], sacc[i][1]), fmaxf(sacc[i][2], sacc[i][3]));
#pragma unroll
            for (int off = 8; off >= 1; off >>= 1)
                mt = fmaxf(mt, __shfl_xor_sync(0xffffffffu, mt, off, 16));
            float mn    = fmaxf(m_i[i], mt);
            float alpha = expf(m_i[i] - mn);
            float lsum = 0.f;
#pragma unroll
            for (int jj = 0; jj < 4; jj++) {
                float p = expf(sacc[i][jj] - mn);
                sacc[i][jj] = p;
                lsum += p;
            }
#pragma unroll
            for (int off = 8; off >= 1; off >>= 1)
                lsum += __shfl_xor_sync(0xffffffffu, lsum, off, 16);
            l_i[i] = l_i[i] * alpha + lsum;
            m_i[i] = mn;
#pragma unroll
            for (int jj = 0; jj < 8; jj++) o_acc[i][jj] *= alpha;
#pragma unroll
            for (int jj = 0; jj < 4; jj++)
                Ps[(ty * 4 + i) * PSTR + tx * 4 + jj] = sacc[i][jj];
        }
        __syncthreads();   // Ps visible; all K reads done

        // ---- load V over KVs ----
        for (int t = tid; t < BKV * 32; t += 512) {
            int r = t >> 5, c4 = (t & 31) << 2;
            *(float4*)&KVs[r * KSTR + c4] =
                *(const float4*)&V[(size_t)(k0 + r) * (NKV * HD) + kvh * HD + c4];
        }
        __syncthreads();

        // ---- O += P @ V (4 rows x 8 dims per thread) ----
#pragma unroll 4
        for (int c = 0; c < BKV; c++) {
            float4 v0 = *(const float4*)&KVs[c * KSTR + tx * 8];
            float4 v1 = *(const float4*)&KVs[c * KSTR + tx * 8 + 4];
#pragma unroll
            for (int i = 0; i < 4; i++) {
                float p = Ps[(ty * 4 + i) * PSTR + c];
                o_acc[i][0] = fmaf(p, v0.x, o_acc[i][0]);
                o_acc[i][1] = fmaf(p, v0.y, o_acc[i][1]);
                o_acc[i][2] = fmaf(p, v0.z, o_acc[i][2]);
                o_acc[i][3] = fmaf(p, v0.w, o_acc[i][3]);
                o_acc[i][4] = fmaf(p, v1.x, o_acc[i][4]);
                o_acc[i][5] = fmaf(p, v1.y, o_acc[i][5]);
                o_acc[i][6] = fmaf(p, v1.z, o_acc[i][6]);
                o_acc[i][7] = fmaf(p, v1.w, o_acc[i][7]);
            }
        }
    }

    // ---- epilogue: O / l ----
#pragma unroll
    for (int i = 0; i < 4; i++) {
        float inv = 1.f / l_i[i];
        float* Orow = O + (size_t)(q0 + ty * 4 + i) * (NH * HD) + h * HD + tx * 8;
        *(float4*)(Orow)     = make_float4(o_acc[i][0] * inv, o_acc[i][1] * inv,
                                           o_acc[i][2] * inv, o_acc[i][3] * inv);
        *(float4*)(Orow + 4) = make_float4(o_acc[i][4] * inv, o_acc[i][5] * inv,
                                           o_acc[i][6] * inv, o_acc[i][7] * inv);
    }
}

// ================= launcher =================
extern "C" void kernel_launch(void* const* d_in, const int* in_sizes, int n_in,
                              void* d_out, int out_size)
{
    const float* X  = (const float*)d_in[0];
    const float* Wq = (const float*)d_in[1];
    const float* Wk = (const float*)d_in[2];
    const float* Wv = (const float*)d_in[3];
    const float* Wo = (const float*)d_in[4];
    float* out = (float*)d_out;

    float *Qp, *Kp, *Vp, *Ap;
    cudaGetSymbolAddress((void**)&Qp, g_Q);
    cudaGetSymbolAddress((void**)&Kp, g_K);
    cudaGetSymbolAddress((void**)&Vp, g_V);
    cudaGetSymbolAddress((void**)&Ap, g_attn);

    dim3 blk(256);
    const int gemm_smem = NSTAGE * STAGE_ELEMS * (int)sizeof(float);  // 56832 B
    cudaFuncSetAttribute(sgemm_tf32,     cudaFuncAttributeMaxDynamicSharedMemorySize, gemm_smem);
    cudaFuncSetAttribute(sgemm_tf32_qkv, cudaFuncAttributeMaxDynamicSharedMemorySize, gemm_smem);

    // fused QKV projection (swizzled grid)
    sgemm_tf32_qkv<<<dim3(48, S_LEN / 128), blk, gemm_smem>>>(X, Wq, Wk, Wv, Qp, Kp, Vp);

    // RoPE on Q and K
    int tq = S_LEN * NH * 16;
    int tk = S_LEN * NKV * 16;
    rope_kernel<<<(tq + 255) / 256, 256>>>(Qp, NH);
    rope_kernel<<<(tk + 255) / 256, 256>>>(Kp, NKV);

    // flash attention (fp32, BQ=128, 512 threads)
    const int fsmem = (BQ * KSTR + BKV * KSTR + BQ * PSTR) * (int)sizeof(float);  // 134656 B
    cudaFuncSetAttribute(flash_kernel, cudaFuncAttributeMaxDynamicSharedMemorySize, fsmem);
    flash_kernel<<<dim3(S_LEN / BQ, NH), 512, fsmem>>>(Qp, Kp, Vp, Ap);

    // output projection (swizzled grid)
    sgemm_tf32<<<dim3(HID / 128, S_LEN / 128), blk, gemm_smem>>>(Ap, Wo, out, S_LEN, HID, HID);
}

// round 17
// speedup vs baseline: 1.4531x; 1.4531x over previous
#include <cuda_runtime.h>
#include <math.h>
#include <stdint.h>

#define S_LEN 2048
#define HID   4096
#define NH    32
#define NKV   8
#define HD    128

// -------- scratch (device globals; no allocation allowed) --------
__device__ float g_Q[S_LEN * NH * HD];     // 32 MB
__device__ float g_K[S_LEN * NKV * HD];    // 8 MB
__device__ float g_V[S_LEN * NKV * HD];    // 8 MB
__device__ float g_attn[S_LEN * NH * HD];  // 32 MB

// ---------------- tf32 helpers ----------------
__device__ __forceinline__ uint32_t frag_tf32(float x) {
    uint32_t u;
    asm("cvt.rna.tf32.f32 %0, %1;" : "=r"(u) : "f"(x));
    return u;
}

__device__ __forceinline__ void mma_tf32(float& d0, float& d1, float& d2, float& d3,
                                         uint32_t a0, uint32_t a1, uint32_t a2, uint32_t a3,
                                         uint32_t b0, uint32_t b1) {
    asm volatile(
        "mma.sync.aligned.m16n8k8.row.col.f32.tf32.tf32.f32 "
        "{%0,%1,%2,%3}, {%4,%5,%6,%7}, {%8,%9}, {%0,%1,%2,%3};"
        : "+f"(d0), "+f"(d1), "+f"(d2), "+f"(d3)
        : "r"(a0), "r"(a1), "r"(a2), "r"(a3), "r"(b0), "r"(b1));
}

__device__ __forceinline__ void cp_async16(uint32_t smem_addr, const void* gptr) {
    asm volatile("cp.async.cg.shared.global [%0], [%1], 16;\n"
                 :: "r"(smem_addr), "l"(gptr));
}
__device__ __forceinline__ void cp_commit() {
    asm volatile("cp.async.commit_group;\n" ::: "memory");
}
template <int N>
__device__ __forceinline__ void cp_wait() {
    asm volatile("cp.async.wait_group %0;\n" :: "n"(N) : "memory");
}

// L2-locality swizzle (kept from R15)
__device__ __forceinline__ void swizzle_bid(int& bm, int& bn) {
    const int gx = gridDim.x, gy = gridDim.y;
    int lin  = blockIdx.y * gx + blockIdx.x;
    int band = 16 * gy;
    int gid  = lin / band;
    int rem  = lin - gid * band;
    bn = gid * 16 + (rem & 15);
    bm = rem >> 4;
}

// ============ TF32 GEMM core (unchanged from R15) ============
#define APITCH 20
#define BPITCH 136
#define A_ELEMS (128 * APITCH)
#define B_ELEMS (16 * BPITCH)
#define STAGE_ELEMS (A_ELEMS + B_ELEMS)
#define NSTAGE 3

__device__ __forceinline__ void gemm_tile_tf32(
    const float* __restrict__ Ag0, int K,
    const float* __restrict__ Bg0, int NB,
    float* __restrict__ Ct, int NC, float* smem)
{
    const int tid  = threadIdx.x;
    const int lane = tid & 31;
    const int wid  = tid >> 5;
    const int warp_m = wid & 1;
    const int warp_n = wid >> 1;
    const int r = lane >> 2;
    const int c = lane & 3;

    const int am  = tid >> 1;
    const int ak8 = (tid & 1) * 8;
    const int bk  = tid >> 4;
    const int bn0 = (tid & 15) * 8;

    const float* Ag = Ag0 + (size_t)am * K + ak8;
    const float* Bg = Bg0 + (size_t)bk * NB + bn0;

    uint32_t smem_base;
    asm("{ .reg .u64 t; cvta.to.shared.u64 t, %1; cvt.u32.u64 %0, t; }"
        : "=r"(smem_base) : "l"(smem));

    float acc[4][4][4];
#pragma unroll
    for (int f = 0; f < 4; f++)
#pragma unroll
        for (int g = 0; g < 4; g++)
#pragma unroll
            for (int x = 0; x < 4; x++) acc[f][g][x] = 0.f;

    const int ntiles = K >> 4;

#pragma unroll
    for (int pf = 0; pf < 2; pf++) {
        uint32_t sa = smem_base + (pf * STAGE_ELEMS + am * APITCH + ak8) * 4;
        cp_async16(sa,      Ag + (size_t)pf * 16);
        cp_async16(sa + 16, Ag + (size_t)pf * 16 + 4);
        uint32_t sb = smem_base + (pf * STAGE_ELEMS + A_ELEMS + bk * BPITCH + bn0) * 4;
        cp_async16(sb,      Bg + (size_t)pf * 16 * NB);
        cp_async16(sb + 16, Bg + (size_t)pf * 16 * NB + 4);
        cp_commit();
    }

    for (int kt = 0; kt < ntiles; kt++) {
        cp_wait<1>();
        __syncthreads();

        if (kt + 2 < ntiles) {
            int st = (kt + 2) % NSTAGE;
            uint32_t sa = smem_base + (st * STAGE_ELEMS + am * APITCH + ak8) * 4;
            cp_async16(sa,      Ag + (size_t)(kt + 2) * 16);
            cp_async16(sa + 16, Ag + (size_t)(kt + 2) * 16 + 4);
            uint32_t sb = smem_base + (st * STAGE_ELEMS + A_ELEMS + bk * BPITCH + bn0) * 4;
            cp_async16(sb,      Bg + (size_t)(kt + 2) * 16 * NB);
            cp_async16(sb + 16, Bg + (size_t)(kt + 2) * 16 * NB + 4);
        }
        cp_commit();

        const float* As = smem + (kt % NSTAGE) * STAGE_ELEMS;
        const float* Bs = As + A_ELEMS;

#pragma unroll
        for (int s = 0; s < 2; s++) {
            const int k0 = s * 8;
            uint32_t af[4][4], bf[4][2];
#pragma unroll
            for (int f = 0; f < 4; f++) {
                const int mb = warp_m * 64 + f * 16;
                af[f][0] = frag_tf32(As[(mb + r    ) * APITCH + k0 + c    ]);
                af[f][1] = frag_tf32(As[(mb + r + 8) * APITCH + k0 + c    ]);
                af[f][2] = frag_tf32(As[(mb + r    ) * APITCH + k0 + c + 4]);
                af[f][3] = frag_tf32(As[(mb + r + 8) * APITCH + k0 + c + 4]);
            }
#pragma unroll
            for (int g = 0; g < 4; g++) {
                const int nb = warp_n * 32 + g * 8;
                bf[g][0] = frag_tf32(Bs[(k0 + c    ) * BPITCH + nb + r]);
                bf[g][1] = frag_tf32(Bs[(k0 + c + 4) * BPITCH + nb + r]);
            }
#pragma unroll
            for (int f = 0; f < 4; f++)
#pragma unroll
                for (int g = 0; g < 4; g++)
                    mma_tf32(acc[f][g][0], acc[f][g][1], acc[f][g][2], acc[f][g][3],
                             af[f][0], af[f][1], af[f][2], af[f][3],
                             bf[g][0], bf[g][1]);
        }
    }

#pragma unroll
    for (int f = 0; f < 4; f++) {
        const int row0 = warp_m * 64 + f * 16 + r;
#pragma unroll
        for (int g = 0; g < 4; g++) {
            const int col0 = warp_n * 32 + g * 8 + 2 * c;
            *(float2*)&Ct[(size_t)row0 * NC + col0]       = make_float2(acc[f][g][0], acc[f][g][1]);
            *(float2*)&Ct[(size_t)(row0 + 8) * NC + col0] = make_float2(acc[f][g][2], acc[f][g][3]);
        }
    }
}

__global__ __launch_bounds__(256, 2)
void sgemm_tf32(const float* __restrict__ A, const float* __restrict__ B,
                float* __restrict__ C, int M, int N, int K)
{
    extern __shared__ float smem[];
    int bm, bn;
    swizzle_bid(bm, bn);
    gemm_tile_tf32(A + (size_t)bm * 128 * K, K,
                   B + (size_t)bn * 128, N,
                   C + (size_t)bm * 128 * N + (size_t)bn * 128, N, smem);
}

__global__ __launch_bounds__(256, 2)
void sgemm_tf32_qkv(const float* __restrict__ X,
                    const float* __restrict__ Wq, const float* __restrict__ Wk,
                    const float* __restrict__ Wv,
                    float* __restrict__ Qo, float* __restrict__ Ko,
                    float* __restrict__ Vo)
{
    extern __shared__ float smem[];
    int bm, bn;
    swizzle_bid(bm, bn);

    const float* Bb;
    float* Cb;
    int Nw, bnl;
    if (bn < 32)      { Bb = Wq; Cb = Qo; Nw = NH * HD;  bnl = bn; }
    else if (bn < 40) { Bb = Wk; Cb = Ko; Nw = NKV * HD; bnl = bn - 32; }
    else              { Bb = Wv; Cb = Vo; Nw = NKV * HD; bnl = bn - 40; }

    gemm_tile_tf32(X + (size_t)bm * 128 * HID, HID,
                   Bb + (size_t)bnl * 128, Nw,
                   Cb + (size_t)bm * 128 * Nw + (size_t)bnl * 128, Nw, smem);
}

// ================= llama3-smoothed RoPE (unchanged) =================
__global__ __launch_bounds__(256)
void rope_kernel(float* __restrict__ x, int nheads)
{
    int idx = blockIdx.x * blockDim.x + threadIdx.x;
    int total = S_LEN * nheads * 16;
    if (idx >= total) return;
    int g = idx & 15;
    int h = (idx >> 4) % nheads;
    int s = idx / (16 * nheads);

    const float LOG2_BASE = 18.93156856932417f;   // log2(500000)
    const float TWO_PI    = 6.283185307179586f;

    float* row = x + (size_t)s * nheads * HD + h * HD;
    float4 v1 = *(float4*)&row[g * 4];
    float4 v2 = *(float4*)&row[g * 4 + 64];

    float o1[4], o2[4];
#pragma unroll
    for (int t = 0; t < 4; t++) {
        int i = g * 4 + t;
        float inv_freq = exp2f(-((float)(2 * i) / 128.0f) * LOG2_BASE);
        float wavelen  = TWO_PI / inv_freq;
        float smooth   = (8192.0f / wavelen - 1.0f) * (1.0f / 3.0f);
        smooth = fminf(1.0f, fmaxf(0.0f, smooth));
        float freq = (1.0f - smooth) * (inv_freq * 0.125f) + smooth * inv_freq;

        float c, sn;
        sincosf((float)s * freq, &sn, &c);
        float x1 = (&v1.x)[t], x2 = (&v2.x)[t];
        o1[t] = x1 * c - x2 * sn;
        o2[t] = x2 * c + x1 * sn;
    }
    *(float4*)&row[g * 4]      = make_float4(o1[0], o1[1], o1[2], o1[3]);
    *(float4*)&row[g * 4 + 64] = make_float4(o2[0], o2[1], o2[2], o2[3]);
}

// ===== Flash attention (causal, GQA), fp32, BQ=128, 256 threads, XOR swizzle ====
// smem pitch 128 (no pad); float4 chunk c of row r lives at chunk c ^ ((r>>2)&7).
// K frag loads (rows 4tx+i) and V loads (chunks 2tx) become conflict-free.
#define BQ 128
#define BKV 64
#define PSTR 65

__device__ __forceinline__ int swz_off(int row, int col) {
    // col multiple of 4; returns float index within tile
    return row * 128 + ((((col >> 2) ^ ((row >> 2) & 7)) << 2) | (col & 3));
}

__global__ __launch_bounds__(256, 1)
void flash_kernel(const float* __restrict__ Q, const float* __restrict__ K,
                  const float* __restrict__ V, float* __restrict__ O)
{
    extern __shared__ float sm[];
    float* Qs  = sm;                          // [128][128] swizzled
    float* KVs = sm + BQ * 128;               // [64][128] swizzled (K then V)
    float* Ps  = sm + BQ * 128 + BKV * 128;   // [128][65]

    const int qt  = gridDim.x - 1 - blockIdx.x;   // longest blocks first
    const int h   = blockIdx.y;
    const int kvh = h >> 2;
    const int tid = threadIdx.x;
    const int tx = tid & 15, ty = tid >> 4;
    const int q0 = qt * BQ;
    const float scale = 0.08838834764831845f;

    // load Q tile (coalesced float4, swizzled store)
    for (int t = tid; t < BQ * 32; t += 256) {
        int r = t >> 5, cc = t & 31;
        int sc = cc ^ ((r >> 2) & 7);
        *(float4*)&Qs[r * 128 + sc * 4] =
            *(const float4*)&Q[(size_t)(q0 + r) * (NH * HD) + h * HD + cc * 4];
    }

    float m_i[8], l_i[8], o_acc[8][8];
#pragma unroll
    for (int i = 0; i < 8; i++) {
        m_i[i] = -INFINITY;
        l_i[i] = 0.f;
#pragma unroll
        for (int j = 0; j < 8; j++) o_acc[i][j] = 0.f;
    }

    const int njt = 2 * qt + 2;
    for (int j = 0; j < njt; j++) {
        const int k0 = j * BKV;
        __syncthreads();
        for (int t = tid; t < BKV * 32; t += 256) {
            int r = t >> 5, cc = t & 31;
            int sc = cc ^ ((r >> 2) & 7);
            *(float4*)&KVs[r * 128 + sc * 4] =
                *(const float4*)&K[(size_t)(k0 + r) * (NKV * HD) + kvh * HD + cc * 4];
        }
        __syncthreads();

        // ---- S = Q K^T (8x4 per thread) ----
        float sacc[8][4];
#pragma unroll
        for (int i = 0; i < 8; i++)
#pragma unroll
            for (int jj = 0; jj < 4; jj++) sacc[i][jj] = 0.f;

#pragma unroll 4
        for (int d = 0; d < HD; d += 4) {
            float4 qa[8], kb[4];
#pragma unroll
            for (int i = 0; i < 8; i++)
                qa[i] = *(const float4*)&Qs[swz_off(ty * 8 + i, d)];
#pragma unroll
            for (int i = 0; i < 4; i++)
                kb[i] = *(const float4*)&KVs[swz_off(tx * 4 + i, d)];
#pragma unroll
            for (int i = 0; i < 8; i++)
#pragma unroll
                for (int jj = 0; jj < 4; jj++) {
                    sacc[i][jj] = fmaf(qa[i].x, kb[jj].x, sacc[i][jj]);
                    sacc[i][jj] = fmaf(qa[i].y, kb[jj].y, sacc[i][jj]);
                    sacc[i][jj] = fmaf(qa[i].z, kb[jj].z, sacc[i][jj]);
                    sacc[i][jj] = fmaf(qa[i].w, kb[jj].w, sacc[i][jj]);
                }
        }

        // ---- scale + causal mask (last two tiles only) ----
        const bool diag = (j >= njt - 2);
#pragma unroll
        for (int i = 0; i < 8; i++)
#pragma unroll
            for (int jj = 0; jj < 4; jj++) {
                float v = sacc[i][jj] * scale;
                if (diag && (k0 + tx * 4 + jj) > (q0 + ty * 8 + i)) v = -INFINITY;
                sacc[i][jj] = v;
            }

        // ---- online softmax ----
#pragma unroll
        for (int i = 0; i < 8; i++) {
            float mt = fmaxf(fmaxf(sacc[i][0], sacc[i][1]), fmaxf(sacc[i][2], sacc[i][3]));
#pragma unroll
            for (int off = 8; off >= 1; off >>= 1)
                mt = fmaxf(mt, __shfl_xor_sync(0xffffffffu, mt, off, 16));
            float mn    = fmaxf(m_i[i], mt);
            float alpha = expf(m_i[i] - mn);
            float lsum = 0.f;
#pragma unroll
            for (int jj = 0; jj < 4; jj++) {
                float p = expf(sacc[i][jj] - mn);
                sacc[i][jj] = p;
                lsum += p;
            }
#pragma unroll
            for (int off = 8; off >= 1; off >>= 1)
                lsum += __shfl_xor_sync(0xffffffffu, lsum, off, 16);
            l_i[i] = l_i[i] * alpha + lsum;
            m_i[i] = mn;
#pragma unroll
            for (int jj = 0; jj < 8; jj++) o_acc[i][jj] *= alpha;
#pragma unroll
            for (int jj = 0; jj < 4; jj++)
                Ps[(ty * 8 + i) * PSTR + tx * 4 + jj] = sacc[i][jj];
        }
        __syncthreads();

        // ---- load V over KVs (swizzled) ----
        for (int t = tid; t < BKV * 32; t += 256) {
            int r = t >> 5, cc = t & 31;
            int sc = cc ^ ((r >> 2) & 7);
            *(float4*)&KVs[r * 128 + sc * 4] =
                *(const float4*)&V[(size_t)(k0 + r) * (NKV * HD) + kvh * HD + cc * 4];
        }
        __syncthreads();

        // ---- O += P @ V (8 rows x 8 dims per thread) ----
#pragma unroll 4
        for (int c = 0; c < BKV; c++) {
            float4 v0 = *(const float4*)&KVs[swz_off(c, tx * 8)];
            float4 v1 = *(const float4*)&KVs[swz_off(c, tx * 8 + 4)];
#pragma unroll
            for (int i = 0; i < 8; i++) {
                float p = Ps[(ty * 8 + i) * PSTR + c];
                o_acc[i][0] = fmaf(p, v0.x, o_acc[i][0]);
                o_acc[i][1] = fmaf(p, v0.y, o_acc[i][1]);
                o_acc[i][2] = fmaf(p, v0.z, o_acc[i][2]);
                o_acc[i][3] = fmaf(p, v0.w, o_acc[i][3]);
                o_acc[i][4] = fmaf(p, v1.x, o_acc[i][4]);
                o_acc[i][5] = fmaf(p, v1.y, o_acc[i][5]);
                o_acc[i][6] = fmaf(p, v1.z, o_acc[i][6]);
                o_acc[i][7] = fmaf(p, v1.w, o_acc[i][7]);
            }
        }
    }

    // ---- epilogue: O / l ----
#pragma unroll
    for (int i = 0; i < 8; i++) {
        float inv = 1.f / l_i[i];
        float* Orow = O + (size_t)(q0 + ty * 8 + i) * (NH * HD) + h * HD + tx * 8;
        *(float4*)(Orow)     = make_float4(o_acc[i][0] * inv, o_acc[i][1] * inv,
                                           o_acc[i][2] * inv, o_acc[i][3] * inv);
        *(float4*)(Orow + 4) = make_float4(o_acc[i][4] * inv, o_acc[i][5] * inv,
                                           o_acc[i][6] * inv, o_acc[i][7] * inv);
    }
}

// ================= launcher =================
extern "C" void kernel_launch(void* const* d_in, const int* in_sizes, int n_in,
                              void* d_out, int out_size)
{
    const float* X  = (const float*)d_in[0];
    const float* Wq = (const float*)d_in[1];
    const float* Wk = (const float*)d_in[2];
    const float* Wv = (const float*)d_in[3];
    const float* Wo = (const float*)d_in[4];
    float* out = (float*)d_out;

    float *Qp, *Kp, *Vp, *Ap;
    cudaGetSymbolAddress((void**)&Qp, g_Q);
    cudaGetSymbolAddress((void**)&Kp, g_K);
    cudaGetSymbolAddress((void**)&Vp, g_V);
    cudaGetSymbolAddress((void**)&Ap, g_attn);

    dim3 blk(256);
    const int gemm_smem = NSTAGE * STAGE_ELEMS * (int)sizeof(float);  // 56832 B
    cudaFuncSetAttribute(sgemm_tf32,     cudaFuncAttributeMaxDynamicSharedMemorySize, gemm_smem);
    cudaFuncSetAttribute(sgemm_tf32_qkv, cudaFuncAttributeMaxDynamicSharedMemorySize, gemm_smem);

    // fused QKV projection (swizzled grid)
    sgemm_tf32_qkv<<<dim3(48, S_LEN / 128), blk, gemm_smem>>>(X, Wq, Wk, Wv, Qp, Kp, Vp);

    // RoPE on Q and K
    int tq = S_LEN * NH * 16;
    int tk = S_LEN * NKV * 16;
    rope_kernel<<<(tq + 255) / 256, 256>>>(Qp, NH);
    rope_kernel<<<(tk + 255) / 256, 256>>>(Kp, NKV);

    // flash attention (fp32, BQ=128, 256 threads, XOR-swizzled smem)
    const int fsmem = (BQ * 128 + BKV * 128 + BQ * PSTR) * (int)sizeof(float);  // 131584 B
    cudaFuncSetAttribute(flash_kernel, cudaFuncAttributeMaxDynamicSharedMemorySize, fsmem);
    flash_kernel<<<dim3(S_LEN / BQ, NH), blk, fsmem>>>(Qp, Kp, Vp, Ap);

    // output projection (swizzled grid)
    sgemm_tf32<<<dim3(HID / 128, S_LEN / 128), blk, gemm_smem>>>(Ap, Wo, out, S_LEN, HID, HID);
}